// round 3
// baseline (speedup 1.0000x reference)
#include <cuda_runtime.h>
#include <math.h>

// ---------------- problem constants ----------------
#define MAX_NODES 50000
#define NODE_REC  352            // A1(32) A2(32) B3(96) B4(96) B5(96)

__device__ float g_node[MAX_NODES * NODE_REC];  // per-node precomputed records

// ---- constants derived from the reference's (non-standard) CG formula ----
// alpha0 = 1/sqrt(32*1*2), alpha1 = 1/sqrt(32*1*3)
#define ALPHA0 0.125f
#define ALPHA1 0.10206207261596575f
// path (0,1,1)/(1,0,1) real tensor: diag(2,1,2)/3
#define D0 0.6666666666666666f
#define D1 0.3333333333333333f
// path (1,1,0) real tensor: diag(4,1,4)/sqrt(33)
#define E0 0.6963106238227914f
#define E1 0.17407765595569785f
// path (1,2,1) normalized real CG nonzeros:
//  C[0][0][2]=+N1  C[0][4][0]=-N1  C[2][0][0]=+N1  C[2][4][2]=+N1
//  C[0][2][0]=-N2  C[2][2][2]=-N2  C[1][2][1]=+N2
//  C[1][1][0]=+N3  C[1][3][2]=+N3  C[0][1][1]=+N4  C[2][3][1]=+N4
#define N1 0.48888007f   // 24/sqrt(2410)
#define N2 0.04704256f   // 4/sqrt(7230)
#define N3 0.06111001f   // 3/sqrt(2410)
#define N4 0.12222002f   // 6/sqrt(2410)

// ---------------- per-node precompute: fold weights + path factors into node records ----------------
__global__ void precompute_kernel(const float* __restrict__ feat,
                                  const float* __restrict__ W,
                                  int n_nodes) {
    __shared__ float Ws[5 * 1024];
    for (int i = threadIdx.x; i < 5 * 1024; i += blockDim.x) {
        int p = i >> 10;
        // per-path uniform scalars; per-component factors applied post-accumulation
        float s = (p == 0) ? ALPHA0 : (p == 3) ? ALPHA0 : ALPHA1;
        Ws[i] = s * W[i];
    }
    __syncthreads();

    int lane  = threadIdx.x & 31;
    int warp  = (blockIdx.x * blockDim.x + threadIdx.x) >> 5;
    int nwarp = (gridDim.x * blockDim.x) >> 5;

    for (int n = warp; n < n_nodes; n += nwarp) {
        const float* x = feat + (size_t)n * 128;
        float x0  = x[lane];
        float x10 = x[32 + 3 * lane];
        float x11 = x[33 + 3 * lane];
        float x12 = x[34 + 3 * lane];
        float a1 = 0.f, a2 = 0.f;
        float b3[3] = {0.f, 0.f, 0.f}, b4[3] = {0.f, 0.f, 0.f}, b5[3] = {0.f, 0.f, 0.f};
        #pragma unroll
        for (int u = 0; u < 32; u++) {
            float xu = __shfl_sync(0xFFFFFFFFu, x0,  u);
            float y0 = __shfl_sync(0xFFFFFFFFu, x10, u);
            float y1 = __shfl_sync(0xFFFFFFFFu, x11, u);
            float y2 = __shfl_sync(0xFFFFFFFFu, x12, u);
            float w0 = Ws[          u * 32 + lane];
            float w1 = Ws[1024 +    u * 32 + lane];
            float w2 = Ws[2048 +    u * 32 + lane];
            float w3 = Ws[3072 +    u * 32 + lane];
            float w4 = Ws[4096 +    u * 32 + lane];
            a1 = fmaf(xu, w0, a1);
            a2 = fmaf(xu, w1, a2);
            b3[0] = fmaf(y0, w2, b3[0]); b3[1] = fmaf(y1, w2, b3[1]); b3[2] = fmaf(y2, w2, b3[2]);
            b4[0] = fmaf(y0, w3, b4[0]); b4[1] = fmaf(y1, w3, b4[1]); b4[2] = fmaf(y2, w3, b4[2]);
            b5[0] = fmaf(y0, w4, b5[0]); b5[1] = fmaf(y1, w4, b5[1]); b5[2] = fmaf(y2, w4, b5[2]);
        }
        // fold component-diagonal CG factors
        b3[0] *= D0; b3[1] *= D1; b3[2] *= D0;   // path (1,0,1): diag(2,1,2)/3
        b4[0] *= E0; b4[1] *= E1; b4[2] *= E0;   // path (1,1,0): diag(4,1,4)/sqrt(33)

        float* rec = g_node + (size_t)n * NODE_REC;
        rec[lane]      = a1;
        rec[32 + lane] = a2;
        #pragma unroll
        for (int k = 0; k < 3; k++) {
            rec[ 64 + 32 * k + lane] = b3[k];
            rec[160 + 32 * k + lane] = b4[k];
            rec[256 + 32 * k + lane] = b5[k];
        }
    }
}

// ---------------- per-edge: combine node record with sh, scatter via vector red ----------------
__global__ void edge_kernel(const float* __restrict__ sh,
                            const int* __restrict__ eidx,
                            float* __restrict__ out,
                            int n_edges) {
    __shared__ float buf[8][128];

    int lane   = threadIdx.x & 31;
    int wlocal = threadIdx.x >> 5;
    int warp   = (blockIdx.x * blockDim.x + threadIdx.x) >> 5;
    int nwarp  = (gridDim.x * blockDim.x) >> 5;

    for (int e = warp; e < n_edges; e += nwarp) {
        int src = eidx[e];
        int dst = eidx[n_edges + e];
        const float* s = sh + (size_t)e * 9;
        float s0 = s[0];
        float s1[3] = { s[1], s[2], s[3] };
        float q0 = s[4], q1v = s[5], q2 = s[6], q3 = s[7], q4 = s[8];

        const float* rec = g_node + (size_t)src * NODE_REC;
        float a1 = rec[lane], a2 = rec[32 + lane];
        float b3[3], b4[3], b5[3];
        #pragma unroll
        for (int k = 0; k < 3; k++) {
            b3[k] = rec[ 64 + 32 * k + lane];
            b4[k] = rec[160 + 32 * k + lane];
            b5[k] = rec[256 + 32 * k + lane];
        }

        // path (1,2,1) sh-contraction terms (asymmetric under reference convention)
        float n2q2 = N2 * q2;
        float n1q4 = N1 * q4;
        float n1q0 = N1 * q0;
        float n3q1 = N3 * q1v;
        float n4q1 = N4 * q1v;
        float n3q3 = N3 * q3;
        float n4q3 = N4 * q3;

        // out0: paths (0,0,0) and (1,1,0)
        float m0 = s0 * a1;
        #pragma unroll
        for (int k = 0; k < 3; k++) m0 = fmaf(s1[k], b4[k], m0);

        // out1: paths (0,1,1), (1,0,1), (1,2,1)
        float m1[3];
        m1[0] = fmaf(D0 * s1[0], a2,
                fmaf(s0, b3[0],
                fmaf(-(n2q2 + n1q4), b5[0],
                fmaf(n3q1, b5[1], n1q0 * b5[2]))));
        m1[1] = fmaf(D1 * s1[1], a2,
                fmaf(s0, b3[1],
                fmaf(n4q1, b5[0],
                fmaf(n2q2, b5[1], n4q3 * b5[2]))));
        m1[2] = fmaf(D0 * s1[2], a2,
                fmaf(s0, b3[2],
                fmaf(n1q0, b5[0],
                fmaf(n3q3, b5[1], (n1q4 - n2q2) * b5[2]))));

        // stage [128] message in SMEM, then 32 x red.v4 (16B-aligned) to out[dst]
        float* b = buf[wlocal];
        b[lane]              = m0;
        b[32 + 3 * lane + 0] = m1[0];
        b[32 + 3 * lane + 1] = m1[1];
        b[32 + 3 * lane + 2] = m1[2];
        __syncwarp();
        float4 v4 = *reinterpret_cast<float4*>(b + 4 * lane);
        float* dptr = out + (size_t)dst * 128 + 4 * lane;
        asm volatile("red.global.add.v4.f32 [%0], {%1,%2,%3,%4};"
                     :: "l"(dptr), "f"(v4.x), "f"(v4.y), "f"(v4.z), "f"(v4.w) : "memory");
        __syncwarp();
    }
}

// ---------------- launch ----------------
extern "C" void kernel_launch(void* const* d_in, const int* in_sizes, int n_in,
                              void* d_out, int out_size) {
    const float* feat = (const float*)d_in[0];
    const float* sh   = (const float*)d_in[1];
    const int*   eidx = (const int*)d_in[2];
    const float* W    = (const float*)d_in[3];
    int n_nodes = in_sizes[0] / 128;
    int n_edges = in_sizes[2] / 2;

    cudaMemsetAsync(d_out, 0, (size_t)out_size * sizeof(float));
    precompute_kernel<<<(n_nodes + 7) / 8, 256>>>(feat, W, n_nodes);
    edge_kernel<<<2048, 256>>>(sh, eidx, (float*)d_out, n_edges);
}

// round 4
// speedup vs baseline: 1.0826x; 1.0826x over previous
#include <cuda_runtime.h>
#include <math.h>

// ---------------- problem constants ----------------
#define MAX_NODES 50000
#define NODE_REC  384            // 3 x float4 per lane, 32 lanes

__device__ float g_node[MAX_NODES * NODE_REC];  // per-node precomputed records

// ---- constants derived from the reference's (non-standard) CG formula ----
#define ALPHA0 0.125f
#define ALPHA1 0.10206207261596575f
// path (0,1,1)/(1,0,1) real tensor: diag(2,1,2)/3
#define D0 0.6666666666666666f
#define D1 0.3333333333333333f
// path (1,1,0) real tensor: diag(4,1,4)/sqrt(33)
#define E0 0.6963106238227914f
#define E1 0.17407765595569785f
// path (1,2,1) normalized real CG nonzeros
#define N1 0.48888007f   // 24/sqrt(2410)
#define N2 0.04704256f   // 4/sqrt(7230)
#define N3 0.06111001f   // 3/sqrt(2410)
#define N4 0.12222002f   // 6/sqrt(2410)

// ---------------- per-node precompute: fold weights + path factors into node records ----------------
__global__ void precompute_kernel(const float* __restrict__ feat,
                                  const float* __restrict__ W,
                                  int n_nodes) {
    __shared__ float Ws[5 * 1024];
    for (int i = threadIdx.x; i < 5 * 1024; i += blockDim.x) {
        int p = i >> 10;
        float s = (p == 0) ? ALPHA0 : (p == 3) ? ALPHA0 : ALPHA1;
        Ws[i] = s * W[i];
    }
    __syncthreads();

    int lane  = threadIdx.x & 31;
    int warp  = (blockIdx.x * blockDim.x + threadIdx.x) >> 5;
    int nwarp = (gridDim.x * blockDim.x) >> 5;

    for (int n = warp; n < n_nodes; n += nwarp) {
        const float* x = feat + (size_t)n * 128;
        float x0  = x[lane];
        float x10 = x[32 + 3 * lane];
        float x11 = x[33 + 3 * lane];
        float x12 = x[34 + 3 * lane];
        float a1 = 0.f, a2 = 0.f;
        float b3[3] = {0.f, 0.f, 0.f}, b4[3] = {0.f, 0.f, 0.f}, b5[3] = {0.f, 0.f, 0.f};
        #pragma unroll
        for (int u = 0; u < 32; u++) {
            float xu = __shfl_sync(0xFFFFFFFFu, x0,  u);
            float y0 = __shfl_sync(0xFFFFFFFFu, x10, u);
            float y1 = __shfl_sync(0xFFFFFFFFu, x11, u);
            float y2 = __shfl_sync(0xFFFFFFFFu, x12, u);
            float w0 = Ws[          u * 32 + lane];
            float w1 = Ws[1024 +    u * 32 + lane];
            float w2 = Ws[2048 +    u * 32 + lane];
            float w3 = Ws[3072 +    u * 32 + lane];
            float w4 = Ws[4096 +    u * 32 + lane];
            a1 = fmaf(xu, w0, a1);
            a2 = fmaf(xu, w1, a2);
            b3[0] = fmaf(y0, w2, b3[0]); b3[1] = fmaf(y1, w2, b3[1]); b3[2] = fmaf(y2, w2, b3[2]);
            b4[0] = fmaf(y0, w3, b4[0]); b4[1] = fmaf(y1, w3, b4[1]); b4[2] = fmaf(y2, w3, b4[2]);
            b5[0] = fmaf(y0, w4, b5[0]); b5[1] = fmaf(y1, w4, b5[1]); b5[2] = fmaf(y2, w4, b5[2]);
        }
        // fold component-diagonal CG factors
        b3[0] *= D0; b3[1] *= D1; b3[2] *= D0;   // path (1,0,1): diag(2,1,2)/3
        b4[0] *= E0; b4[1] *= E1; b4[2] *= E0;   // path (1,1,0): diag(4,1,4)/sqrt(33)

        float4* rec4 = (float4*)(g_node + (size_t)n * NODE_REC);
        rec4[lane]      = make_float4(a1, a2, b3[0], b3[1]);
        rec4[32 + lane] = make_float4(b3[2], b4[0], b4[1], b4[2]);
        rec4[64 + lane] = make_float4(b5[0], b5[1], b5[2], 0.f);
    }
}

// ---------------- per-edge: gather record, combine with sh, shuffle-transpose, red.v4 ----------------
__global__ void __launch_bounds__(256) edge_kernel(const float* __restrict__ sh,
                                                   const int* __restrict__ eidx,
                                                   float* __restrict__ out,
                                                   int n_edges) {
    const unsigned FULL = 0xFFFFFFFFu;
    int lane  = threadIdx.x & 31;
    int warp  = (blockIdx.x * blockDim.x + threadIdx.x) >> 5;
    int nwarp = (gridDim.x * blockDim.x) >> 5;

    int e = warp;
    int src = 0, dst = 0;
    float sv = 0.f;
    if (e < n_edges) {
        src = eidx[e];
        dst = eidx[n_edges + e];
        sv  = (lane < 9) ? sh[(size_t)e * 9 + lane] : 0.f;
    }

    while (e < n_edges) {
        // issue record gather first (longest latency)
        const float4* rec4 = (const float4*)(g_node + (size_t)src * NODE_REC);
        float4 r0 = rec4[lane];
        float4 r1 = rec4[32 + lane];
        float4 r2 = rec4[64 + lane];

        // prefetch next edge's idx + sh while the gather is in flight
        int en = e + nwarp;
        int nsrc = 0, ndst = 0;
        float nsv = 0.f;
        if (en < n_edges) {
            nsrc = eidx[en];
            ndst = eidx[n_edges + en];
            nsv  = (lane < 9) ? sh[(size_t)en * 9 + lane] : 0.f;
        }

        // broadcast sh components
        float s0  = __shfl_sync(FULL, sv, 0);
        float s1x = __shfl_sync(FULL, sv, 1);
        float s1y = __shfl_sync(FULL, sv, 2);
        float s1z = __shfl_sync(FULL, sv, 3);
        float q0  = __shfl_sync(FULL, sv, 4);
        float q1v = __shfl_sync(FULL, sv, 5);
        float q2  = __shfl_sync(FULL, sv, 6);
        float q3  = __shfl_sync(FULL, sv, 7);
        float q4  = __shfl_sync(FULL, sv, 8);

        // path (1,2,1) sh-contraction terms
        float n2q2 = N2 * q2;
        float n1q4 = N1 * q4;
        float n1q0 = N1 * q0;
        float n3q1 = N3 * q1v;
        float n4q1 = N4 * q1v;
        float n3q3 = N3 * q3;
        float n4q3 = N4 * q3;

        float a1 = r0.x, a2 = r0.y;
        float b3x = r0.z, b3y = r0.w, b3z = r1.x;
        float b4x = r1.y, b4y = r1.z, b4z = r1.w;
        float b5x = r2.x, b5y = r2.y, b5z = r2.z;

        // out0: paths (0,0,0) and (1,1,0)
        float m0 = s0 * a1;
        m0 = fmaf(s1x, b4x, m0);
        m0 = fmaf(s1y, b4y, m0);
        m0 = fmaf(s1z, b4z, m0);

        // out1: paths (0,1,1), (1,0,1), (1,2,1)
        float m1x = fmaf(D0 * s1x, a2,
                    fmaf(s0, b3x,
                    fmaf(-(n2q2 + n1q4), b5x,
                    fmaf(n3q1, b5y, n1q0 * b5z))));
        float m1y = fmaf(D1 * s1y, a2,
                    fmaf(s0, b3y,
                    fmaf(n4q1, b5x,
                    fmaf(n2q2, b5y, n4q3 * b5z))));
        float m1z = fmaf(D0 * s1z, a2,
                    fmaf(s0, b3z,
                    fmaf(n1q0, b5x,
                    fmaf(n3q3, b5y, (n1q4 - n2q2) * b5z))));

        // shuffle-transpose: lane l gathers out positions 4l..4l+3
        //   p < 32      -> m0 of lane p
        //   p >= 32     -> m1[k] of lane w, where w=(p-32)/3, k=(p-32)%3
        float v[4];
        #pragma unroll
        for (int j = 0; j < 4; j++) {
            int p = 4 * lane + j;
            int q = p - 32;
            int w = (q >= 0) ? (q / 3) : 0;
            int k = q - 3 * w;
            int sl = (p < 32) ? p : w;
            float t0 = __shfl_sync(FULL, m0,  sl);
            float t1 = __shfl_sync(FULL, m1x, sl);
            float t2 = __shfl_sync(FULL, m1y, sl);
            float t3 = __shfl_sync(FULL, m1z, sl);
            v[j] = (p < 32) ? t0 : ((k == 0) ? t1 : (k == 1) ? t2 : t3);
        }

        float* dptr = out + (size_t)dst * 128 + 4 * lane;
        asm volatile("red.global.add.v4.f32 [%0], {%1,%2,%3,%4};"
                     :: "l"(dptr), "f"(v[0]), "f"(v[1]), "f"(v[2]), "f"(v[3]) : "memory");

        e = en; src = nsrc; dst = ndst; sv = nsv;
    }
}

// ---------------- launch ----------------
extern "C" void kernel_launch(void* const* d_in, const int* in_sizes, int n_in,
                              void* d_out, int out_size) {
    const float* feat = (const float*)d_in[0];
    const float* sh   = (const float*)d_in[1];
    const int*   eidx = (const int*)d_in[2];
    const float* W    = (const float*)d_in[3];
    int n_nodes = in_sizes[0] / 128;
    int n_edges = in_sizes[2] / 2;

    cudaMemsetAsync(d_out, 0, (size_t)out_size * sizeof(float));
    precompute_kernel<<<(n_nodes + 7) / 8, 256>>>(feat, W, n_nodes);
    edge_kernel<<<2048, 256>>>(sh, eidx, (float*)d_out, n_edges);
}

// round 5
// speedup vs baseline: 1.3394x; 1.2372x over previous
#include <cuda_runtime.h>
#include <cuda_fp16.h>
#include <math.h>

// ---------------- problem constants ----------------
#define MAX_NODES 50000

// fp16-compressed per-node records: per lane 12 halves = uint4 (8 halves) + uint2 (4 halves)
__device__ uint4 g_node4[MAX_NODES * 32];
__device__ uint2 g_node2[MAX_NODES * 32];

// ---- constants derived from the reference's (non-standard) CG formula ----
#define ALPHA0 0.125f
#define ALPHA1 0.10206207261596575f
// path (0,1,1)/(1,0,1) real tensor: diag(2,1,2)/3
#define D0 0.6666666666666666f
#define D1 0.3333333333333333f
// path (1,1,0) real tensor: diag(4,1,4)/sqrt(33)
#define E0 0.6963106238227914f
#define E1 0.17407765595569785f
// path (1,2,1) normalized real CG nonzeros
#define N1 0.48888007f   // 24/sqrt(2410)
#define N2 0.04704256f   // 4/sqrt(7230)
#define N3 0.06111001f   // 3/sqrt(2410)
#define N4 0.12222002f   // 6/sqrt(2410)

static __device__ __forceinline__ unsigned pack2(float a, float b) {
    half2 h = __floats2half2_rn(a, b);
    return *reinterpret_cast<unsigned*>(&h);
}
static __device__ __forceinline__ float2 unpack2(unsigned u) {
    half2 h = *reinterpret_cast<half2*>(&u);
    return __half22float2(h);
}

// ---------------- per-node precompute: fold weights + path factors, store fp16 ----------------
__global__ void precompute_kernel(const float* __restrict__ feat,
                                  const float* __restrict__ W,
                                  int n_nodes) {
    __shared__ float Ws[5 * 1024];
    for (int i = threadIdx.x; i < 5 * 1024; i += blockDim.x) {
        int p = i >> 10;
        float s = (p == 0) ? ALPHA0 : (p == 3) ? ALPHA0 : ALPHA1;
        Ws[i] = s * W[i];
    }
    __syncthreads();

    int lane  = threadIdx.x & 31;
    int warp  = (blockIdx.x * blockDim.x + threadIdx.x) >> 5;
    int nwarp = (gridDim.x * blockDim.x) >> 5;

    for (int n = warp; n < n_nodes; n += nwarp) {
        const float* x = feat + (size_t)n * 128;
        float x0  = x[lane];
        float x10 = x[32 + 3 * lane];
        float x11 = x[33 + 3 * lane];
        float x12 = x[34 + 3 * lane];
        float a1 = 0.f, a2 = 0.f;
        float b3[3] = {0.f, 0.f, 0.f}, b4[3] = {0.f, 0.f, 0.f}, b5[3] = {0.f, 0.f, 0.f};
        #pragma unroll
        for (int u = 0; u < 32; u++) {
            float xu = __shfl_sync(0xFFFFFFFFu, x0,  u);
            float y0 = __shfl_sync(0xFFFFFFFFu, x10, u);
            float y1 = __shfl_sync(0xFFFFFFFFu, x11, u);
            float y2 = __shfl_sync(0xFFFFFFFFu, x12, u);
            float w0 = Ws[          u * 32 + lane];
            float w1 = Ws[1024 +    u * 32 + lane];
            float w2 = Ws[2048 +    u * 32 + lane];
            float w3 = Ws[3072 +    u * 32 + lane];
            float w4 = Ws[4096 +    u * 32 + lane];
            a1 = fmaf(xu, w0, a1);
            a2 = fmaf(xu, w1, a2);
            b3[0] = fmaf(y0, w2, b3[0]); b3[1] = fmaf(y1, w2, b3[1]); b3[2] = fmaf(y2, w2, b3[2]);
            b4[0] = fmaf(y0, w3, b4[0]); b4[1] = fmaf(y1, w3, b4[1]); b4[2] = fmaf(y2, w3, b4[2]);
            b5[0] = fmaf(y0, w4, b5[0]); b5[1] = fmaf(y1, w4, b5[1]); b5[2] = fmaf(y2, w4, b5[2]);
        }
        // fold component-diagonal CG factors
        b3[0] *= D0; b3[1] *= D1; b3[2] *= D0;   // path (1,0,1): diag(2,1,2)/3
        b4[0] *= E0; b4[1] *= E1; b4[2] *= E0;   // path (1,1,0): diag(4,1,4)/sqrt(33)

        uint4 p;
        p.x = pack2(a1,   a2);
        p.y = pack2(b3[0], b3[1]);
        p.z = pack2(b3[2], b4[0]);
        p.w = pack2(b4[1], b4[2]);
        uint2 q;
        q.x = pack2(b5[0], b5[1]);
        q.y = pack2(b5[2], 0.f);
        g_node4[n * 32 + lane] = p;
        g_node2[n * 32 + lane] = q;
    }
}

// ---------------- per-edge: gather fp16 record, combine with sh, shuffle-transpose, red.v4 ----------------
__global__ void __launch_bounds__(256) edge_kernel(const float* __restrict__ sh,
                                                   const int* __restrict__ eidx,
                                                   float* __restrict__ out,
                                                   int n_edges) {
    const unsigned FULL = 0xFFFFFFFFu;
    int lane  = threadIdx.x & 31;
    int warp  = (blockIdx.x * blockDim.x + threadIdx.x) >> 5;
    int nwarp = (gridDim.x * blockDim.x) >> 5;

    // loop-invariant shuffle-transpose control (lane-constant)
    int tp[4], tsl[4], tk[4];
    #pragma unroll
    for (int j = 0; j < 4; j++) {
        int p = 4 * lane + j;
        int q = p - 32;
        int w = (q >= 0) ? (q / 3) : 0;
        tk[j]  = q - 3 * w;
        tsl[j] = (p < 32) ? p : w;
        tp[j]  = (p < 32);
    }

    int e = warp;
    int src = 0, dst = 0;
    float sv = 0.f;
    if (e < n_edges) {
        src = eidx[e];
        dst = eidx[n_edges + e];
        sv  = (lane < 9) ? sh[(size_t)e * 9 + lane] : 0.f;
    }

    while (e < n_edges) {
        // issue record gather first (longest latency)
        uint4 rp = g_node4[src * 32 + lane];
        uint2 rq = g_node2[src * 32 + lane];

        // prefetch next edge's idx + sh while the gather is in flight
        int en = e + nwarp;
        int nsrc = 0, ndst = 0;
        float nsv = 0.f;
        if (en < n_edges) {
            nsrc = eidx[en];
            ndst = eidx[n_edges + en];
            nsv  = (lane < 9) ? sh[(size_t)en * 9 + lane] : 0.f;
        }

        // broadcast sh components
        float s0  = __shfl_sync(FULL, sv, 0);
        float s1x = __shfl_sync(FULL, sv, 1);
        float s1y = __shfl_sync(FULL, sv, 2);
        float s1z = __shfl_sync(FULL, sv, 3);
        float q0  = __shfl_sync(FULL, sv, 4);
        float q1v = __shfl_sync(FULL, sv, 5);
        float q2  = __shfl_sync(FULL, sv, 6);
        float q3  = __shfl_sync(FULL, sv, 7);
        float q4  = __shfl_sync(FULL, sv, 8);

        // path (1,2,1) sh-contraction terms
        float n2q2 = N2 * q2;
        float n1q4 = N1 * q4;
        float n1q0 = N1 * q0;
        float n3q1 = N3 * q1v;
        float n4q1 = N4 * q1v;
        float n3q3 = N3 * q3;
        float n4q3 = N4 * q3;

        float2 u0 = unpack2(rp.x);   // a1, a2
        float2 u1 = unpack2(rp.y);   // b3x, b3y
        float2 u2 = unpack2(rp.z);   // b3z, b4x
        float2 u3 = unpack2(rp.w);   // b4y, b4z
        float2 u4 = unpack2(rq.x);   // b5x, b5y
        float2 u5 = unpack2(rq.y);   // b5z, -
        float a1 = u0.x, a2 = u0.y;
        float b3x = u1.x, b3y = u1.y, b3z = u2.x;
        float b4x = u2.y, b4y = u3.x, b4z = u3.y;
        float b5x = u4.x, b5y = u4.y, b5z = u5.x;

        // out0: paths (0,0,0) and (1,1,0)
        float m0 = s0 * a1;
        m0 = fmaf(s1x, b4x, m0);
        m0 = fmaf(s1y, b4y, m0);
        m0 = fmaf(s1z, b4z, m0);

        // out1: paths (0,1,1), (1,0,1), (1,2,1)
        float m1x = fmaf(D0 * s1x, a2,
                    fmaf(s0, b3x,
                    fmaf(-(n2q2 + n1q4), b5x,
                    fmaf(n3q1, b5y, n1q0 * b5z))));
        float m1y = fmaf(D1 * s1y, a2,
                    fmaf(s0, b3y,
                    fmaf(n4q1, b5x,
                    fmaf(n2q2, b5y, n4q3 * b5z))));
        float m1z = fmaf(D0 * s1z, a2,
                    fmaf(s0, b3z,
                    fmaf(n1q0, b5x,
                    fmaf(n3q3, b5y, (n1q4 - n2q2) * b5z))));

        // shuffle-transpose: lane l gathers out positions 4l..4l+3
        float v[4];
        #pragma unroll
        for (int j = 0; j < 4; j++) {
            float t0 = __shfl_sync(FULL, m0,  tsl[j]);
            float t1 = __shfl_sync(FULL, m1x, tsl[j]);
            float t2 = __shfl_sync(FULL, m1y, tsl[j]);
            float t3 = __shfl_sync(FULL, m1z, tsl[j]);
            v[j] = tp[j] ? t0 : ((tk[j] == 0) ? t1 : (tk[j] == 1) ? t2 : t3);
        }

        float* dptr = out + (size_t)dst * 128 + 4 * lane;
        asm volatile("red.global.add.v4.f32 [%0], {%1,%2,%3,%4};"
                     :: "l"(dptr), "f"(v[0]), "f"(v[1]), "f"(v[2]), "f"(v[3]) : "memory");

        e = en; src = nsrc; dst = ndst; sv = nsv;
    }
}

// ---------------- launch ----------------
extern "C" void kernel_launch(void* const* d_in, const int* in_sizes, int n_in,
                              void* d_out, int out_size) {
    const float* feat = (const float*)d_in[0];
    const float* sh   = (const float*)d_in[1];
    const int*   eidx = (const int*)d_in[2];
    const float* W    = (const float*)d_in[3];
    int n_nodes = in_sizes[0] / 128;
    int n_edges = in_sizes[2] / 2;

    cudaMemsetAsync(d_out, 0, (size_t)out_size * sizeof(float));
    precompute_kernel<<<(n_nodes + 7) / 8, 256>>>(feat, W, n_nodes);
    edge_kernel<<<2048, 256>>>(sh, eidx, (float*)d_out, n_edges);
}